// round 8
// baseline (speedup 1.0000x reference)
#include <cuda_runtime.h>

#define NT 128
#define BB 256
#define SS 512
#define NCTA (BB / 2)

__device__ float g_expT[NT * NT];
__device__ float g_part[BB];
__device__ float g_gold[BB];
__device__ int   g_tags64;   // 1 if tags are int64, 0 if int32
__device__ int   g_mask4;    // 1 if mask is 4-byte, 0 if 1-byte

// ---- packed fp32x2 helpers (sm_100+; ptxas never auto-fuses these) ----
__device__ __forceinline__ unsigned long long pack2(float lo, float hi) {
    unsigned long long r;
    asm("mov.b64 %0, {%1, %2};" : "=l"(r) : "f"(lo), "f"(hi));
    return r;
}
#define FMA2(acc, a, b) \
    asm("fma.rn.f32x2 %0, %1, %2, %0;" : "+l"(acc) : "l"(a), "l"(b))
__device__ __forceinline__ unsigned long long add2(unsigned long long a,
                                                   unsigned long long b) {
    unsigned long long d;
    asm("add.rn.f32x2 %0, %1, %2;" : "=l"(d) : "l"(a), "l"(b));
    return d;
}
__device__ __forceinline__ float hadd2(unsigned long long a) {
    float lo, hi;
    asm("mov.b64 {%0, %1}, %2;" : "=f"(lo), "=f"(hi) : "l"(a));
    return lo + hi;
}

// Detect actual element widths of tags/mask (JAX x64-disabled silently makes
// int64 -> int32). Deterministic given fixed inputs; graph-capturable.
__global__ void detect_kernel(const void* tags, const void* mask) {
    if (threadIdx.x == 0) {
        const unsigned int* tw = (const unsigned int*)tags;
        int is64 = 1;
        for (int k = 0; k < 32; k++)
            if (tw[2 * k + 1] != 0u) is64 = 0;   // high words nonzero -> int32
        g_tags64 = is64;
        unsigned int w0 = ((const unsigned int*)mask)[0];
        g_mask4 = (w0 & 0xFFFFFF00u) ? 0 : 1;    // packed bytes -> 1-byte mask
    }
}

// Precompute exp(T) once per launch (cheap: 16K elements).
__global__ void expT_kernel(const float* __restrict__ T) {
    int idx = blockIdx.x * blockDim.x + threadIdx.x;
    g_expT[idx] = __expf(T[idx]);
}

// One CTA per PAIR of batches. Thread j owns tag column j for both batches;
// expT[:,j] packed in 64 regs is shared across the two recurrences, which
// interleave for ILP (the serial exp->bar->lds->fma->log chain is paid once
// per step for two batches).
__global__ __launch_bounds__(128, 1) void crf_forward_kernel(
    const float* __restrict__ emissions,      // [B, S, NT]
    const void* __restrict__ tags_raw,        // [B, S] int32 or int64
    const void* __restrict__ mask_raw,        // [B, S] 1B or 4B bool
    const float* __restrict__ trans)          // [NT, NT]
{
    const int bA = 2 * blockIdx.x;
    const int bB = bA + 1;
    const int j = threadIdx.x;
    const int lane = j & 31;
    const int wid = j >> 5;

    __shared__ __align__(16) float vshA[2][NT];
    __shared__ __align__(16) float vshB[2][NT];
    __shared__ float mshA[2], mshB[2];
    __shared__ float warpred[4];
    __shared__ float warpsum[4];

    // ---- pack exp(T) column j: eTp[i] = (expT[2i][j], expT[2i+1][j]) ----
    unsigned long long eTp[NT / 2];
#pragma unroll
    for (int i = 0; i < NT / 2; i++)
        eTp[i] = pack2(g_expT[(2 * i) * NT + j], g_expT[(2 * i + 1) * NT + j]);

    const float* eA_ptr = emissions + (size_t)bA * SS * NT;
    const float* eB_ptr = emissions + (size_t)bB * SS * NT;
    float alphaA = eA_ptr[j];          // alpha0
    float alphaB = eB_ptr[j];
    eA_ptr += NT; eB_ptr += NT;

    if (j == 0) { mshA[0] = alphaA; mshB[0] = alphaB; }
    __syncthreads();
    float mA = mshA[0], mB = mshB[0];  // stale-by-one surrogate shifts

    float eA_cur = eA_ptr[j];          // emissions[b, 1, j]
    float eB_cur = eB_ptr[j];
    eA_ptr += NT; eB_ptr += NT;

    // ---- forward recursion, 511 steps; ONE sync per step, 2 batches ----
    int buf = 0;
    for (int t = 1; t < SS; t++) {
        float eA_nxt = 0.f, eB_nxt = 0.f;
        if (t < SS - 1) {
            eA_nxt = eA_ptr[j]; eA_ptr += NT;
            eB_nxt = eB_ptr[j]; eB_ptr += NT;
        }

        vshA[buf][j] = __expf(alphaA - mA);
        vshB[buf][j] = __expf(alphaB - mB);
        if (j == 0) { mshA[buf] = alphaA; mshB[buf] = alphaB; }
        __syncthreads();
        float mA_next = mshA[buf];
        float mB_next = mshB[buf];

        // w[j] = sum_i v[i] * expT[i][j] for both batches, packed 2-wide.
        unsigned long long aA0 = 0ull, aA1 = 0ull, aA2 = 0ull, aA3 = 0ull;
        unsigned long long aB0 = 0ull, aB1 = 0ull, aB2 = 0ull, aB3 = 0ull;
        const ulonglong2* vA = (const ulonglong2*)vshA[buf];
        const ulonglong2* vB = (const ulonglong2*)vshB[buf];
#pragma unroll
        for (int i = 0; i < NT / 4; i += 2) {
            ulonglong2 xa = vA[i];
            ulonglong2 xb = vB[i];
            ulonglong2 ya = vA[i + 1];
            ulonglong2 yb = vB[i + 1];
            FMA2(aA0, xa.x, eTp[2 * i + 0]);
            FMA2(aB0, xb.x, eTp[2 * i + 0]);
            FMA2(aA1, xa.y, eTp[2 * i + 1]);
            FMA2(aB1, xb.y, eTp[2 * i + 1]);
            FMA2(aA2, ya.x, eTp[2 * i + 2]);
            FMA2(aB2, yb.x, eTp[2 * i + 2]);
            FMA2(aA3, ya.y, eTp[2 * i + 3]);
            FMA2(aB3, yb.y, eTp[2 * i + 3]);
        }
        float wA = hadd2(add2(add2(aA0, aA1), add2(aA2, aA3)));
        float wB = hadd2(add2(add2(aB0, aB1), add2(aB2, aB3)));

        alphaA = mA + __logf(wA) + eA_cur;  // same m as the exp above
        alphaB = mB + __logf(wB) + eB_cur;
        mA = mA_next; mB = mB_next;
        eA_cur = eA_nxt; eB_cur = eB_nxt;
        buf ^= 1;
    }

    // ---- partition: exact logsumexp over final alpha, each batch ----
#pragma unroll
    for (int pass = 0; pass < 2; pass++) {
        float alpha = pass ? alphaB : alphaA;
        int b = pass ? bB : bA;
        float wm = alpha;
#pragma unroll
        for (int o = 16; o; o >>= 1)
            wm = fmaxf(wm, __shfl_xor_sync(0xffffffffu, wm, o));
        if (lane == 0) warpred[wid] = wm;
        __syncthreads();
        float mx = fmaxf(fmaxf(warpred[0], warpred[1]),
                         fmaxf(warpred[2], warpred[3]));
        float ex = __expf(alpha - mx);
#pragma unroll
        for (int o = 16; o; o >>= 1)
            ex += __shfl_xor_sync(0xffffffffu, ex, o);
        if (lane == 0) warpsum[wid] = ex;
        __syncthreads();
        if (j == 0) {
            float s = (warpsum[0] + warpsum[1]) + (warpsum[2] + warpsum[3]);
            g_part[b] = mx + __logf(s);
        }
        __syncthreads();
    }

    // ---- gold score for both batches (dtype-adaptive tag/mask reads) ----
    const int tags64 = g_tags64;
    const int mask4 = g_mask4;
#pragma unroll
    for (int pass = 0; pass < 2; pass++) {
        int b = pass ? bB : bA;
        const long long* tg64 = (const long long*)tags_raw + (size_t)b * SS;
        const int* tg32 = (const int*)tags_raw + (size_t)b * SS;
        const int* mk32 = (const int*)mask_raw + (size_t)b * SS;
        const unsigned char* mk8 = (const unsigned char*)mask_raw + (size_t)b * SS;
        const float* em_row = emissions + (size_t)b * SS * NT;

        float g = 0.f;
        for (int t = j; t < SS; t += NT) {
            int tg = tags64 ? (int)tg64[t] : tg32[t];
            int mraw = mask4 ? mk32[t] : (int)mk8[t];
            float mk = mraw ? 1.f : 0.f;
            g += em_row[(size_t)t * NT + tg] * mk;
            if (t > 0) {
                int tp = tags64 ? (int)tg64[t - 1] : tg32[t - 1];
                g += trans[tp * NT + tg] * mk;
            }
        }
#pragma unroll
        for (int o = 16; o; o >>= 1)
            g += __shfl_xor_sync(0xffffffffu, g, o);
        __syncthreads();
        if (lane == 0) warpred[wid] = g;
        __syncthreads();
        if (j == 0)
            g_gold[b] = (warpred[0] + warpred[1]) + (warpred[2] + warpred[3]);
        __syncthreads();
    }
}

// Deterministic final reduction: out = sum_b (part[b] - gold[b]).
__global__ void finish_kernel(float* __restrict__ out) {
    const int b = threadIdx.x;         // 256 threads
    const int lane = b & 31;
    const int wid = b >> 5;
    __shared__ float wsum[8];
    float v = g_part[b] - g_gold[b];
#pragma unroll
    for (int o = 16; o; o >>= 1)
        v += __shfl_xor_sync(0xffffffffu, v, o);
    if (lane == 0) wsum[wid] = v;
    __syncthreads();
    if (b == 0) {
        float s = 0.f;
#pragma unroll
        for (int w = 0; w < 8; w++) s += wsum[w];
        out[0] = s;
    }
}

extern "C" void kernel_launch(void* const* d_in, const int* in_sizes, int n_in,
                              void* d_out, int out_size) {
    const float* emissions = (const float*)d_in[0];
    const void* tags = d_in[1];
    const void* mask = d_in[2];
    const float* trans = (const float*)d_in[3];
    float* out = (float*)d_out;

    detect_kernel<<<1, 32>>>(tags, mask);
    expT_kernel<<<NT, NT>>>(trans);
    crf_forward_kernel<<<NCTA, NT>>>(emissions, tags, mask, trans);
    finish_kernel<<<1, BB>>>(out);
}

// round 10
// speedup vs baseline: 1.2071x; 1.2071x over previous
#include <cuda_runtime.h>

#define NT 128
#define BB 256
#define SS 512

__device__ float g_part[BB];
__device__ float g_gold[BB];

// ---- packed fp32x2 helpers (sm_100+; ptxas never auto-fuses these) ----
__device__ __forceinline__ unsigned long long pack2(float lo, float hi) {
    unsigned long long r;
    asm("mov.b64 %0, {%1, %2};" : "=l"(r) : "f"(lo), "f"(hi));
    return r;
}
#define FMA2(acc, a, b) \
    asm("fma.rn.f32x2 %0, %1, %2, %0;" : "+l"(acc) : "l"(a), "l"(b))
__device__ __forceinline__ unsigned long long add2(unsigned long long a,
                                                   unsigned long long b) {
    unsigned long long d;
    asm("add.rn.f32x2 %0, %1, %2;" : "=l"(d) : "l"(a), "l"(b));
    return d;
}
__device__ __forceinline__ float hadd2(unsigned long long a) {
    float lo, hi;
    asm("mov.b64 {%0, %1}, %2;" : "=f"(lo), "=f"(hi) : "l"(a));
    return lo + hi;
}

// One CTA per batch. Thread j owns tag column j; exp(T[:,j]) packed in 64 regs.
// detect + expT fused into the prologue (fewer launches, no global round-trip).
__global__ __launch_bounds__(128, 2) void crf_forward_kernel(
    const float* __restrict__ emissions,      // [B, S, NT]
    const void* __restrict__ tags_raw,        // [B, S] int32 or int64
    const void* __restrict__ mask_raw,        // [B, S] 1B or 4B bool
    const float* __restrict__ trans)          // [NT, NT]
{
    const int b = blockIdx.x;
    const int j = threadIdx.x;
    const int lane = j & 31;
    const int wid = j >> 5;

    __shared__ __align__(16) float vsh[2][NT];
    __shared__ float msh[2];
    __shared__ float warpred[4];
    __shared__ float warpsum[4];
    __shared__ int sh_tags64, sh_mask4;

    // ---- dtype detection (JAX x64-off silently makes int64 -> int32) ----
    if (j == 0) {
        const unsigned int* tw = (const unsigned int*)tags_raw;
        int is64 = 1;
        for (int k = 0; k < 32; k++)
            if (tw[2 * k + 1] != 0u) is64 = 0;
        sh_tags64 = is64;
        unsigned int w0 = ((const unsigned int*)mask_raw)[0];
        sh_mask4 = (w0 & 0xFFFFFF00u) ? 0 : 1;
    }

    // ---- build exp(T) column j in packed registers directly from trans ----
    unsigned long long eTp[NT / 2];
#pragma unroll
    for (int i = 0; i < NT / 2; i++)
        eTp[i] = pack2(__expf(trans[(2 * i) * NT + j]),
                       __expf(trans[(2 * i + 1) * NT + j]));

    const float* e_ptr = emissions + (size_t)b * SS * NT;
    float alpha = e_ptr[j];            // alpha0 = emissions[b, 0, :]

    if (j == 0) msh[0] = alpha;
    __syncthreads();
    float m = msh[0];                  // stale-by-one surrogate shift

    // depth-2 emission prefetch: e_cur = row1, e_n1 = row2, e_ptr -> row3
    float e_cur = e_ptr[NT + j];
    float e_n1 = e_ptr[2 * NT + j];
    e_ptr += 3 * NT;

    // ---- forward recursion, 511 steps; ONE sync per step ----
    int buf = 0;
#pragma unroll 2
    for (int t = 1; t < SS; t++) {
        // prefetch TWO rows ahead, issued BEFORE the exp/STS/BAR so the LDG
        // is in flight across the whole FMA block
        float e_n2 = 0.f;
        if (t + 2 < SS) { e_n2 = e_ptr[j]; e_ptr += NT; }

        vsh[buf][j] = __expf(alpha - m);
        if (j == 0) msh[buf] = alpha;  // broadcast alpha_t[0] for step t+1
        __syncthreads();
        float m_next = msh[buf];

        // w[j] = sum_i v[i] * expT[i][j], packed 2-wide
        unsigned long long acc0 = 0ull, acc1 = 0ull, acc2 = 0ull, acc3 = 0ull;
        const ulonglong2* v2 = (const ulonglong2*)vsh[buf];
#pragma unroll
        for (int i = 0; i < NT / 4; i += 2) {
            ulonglong2 va = v2[i];
            ulonglong2 vb = v2[i + 1];
            FMA2(acc0, va.x, eTp[2 * i + 0]);
            FMA2(acc1, va.y, eTp[2 * i + 1]);
            FMA2(acc2, vb.x, eTp[2 * i + 2]);
            FMA2(acc3, vb.y, eTp[2 * i + 3]);
        }
        float w = hadd2(add2(add2(acc0, acc1), add2(acc2, acc3)));

        alpha = m + __logf(w) + e_cur; // must use the SAME m as the exp
        m = m_next;
        e_cur = e_n1;
        e_n1 = e_n2;
        buf ^= 1;
    }

    // ---- partition contribution: exact logsumexp over final alpha ----
    {
        float wm = alpha;
#pragma unroll
        for (int o = 16; o; o >>= 1)
            wm = fmaxf(wm, __shfl_xor_sync(0xffffffffu, wm, o));
        if (lane == 0) warpred[wid] = wm;
        __syncthreads();
        float mx = fmaxf(fmaxf(warpred[0], warpred[1]),
                         fmaxf(warpred[2], warpred[3]));
        float ex = __expf(alpha - mx);
#pragma unroll
        for (int o = 16; o; o >>= 1)
            ex += __shfl_xor_sync(0xffffffffu, ex, o);
        if (lane == 0) warpsum[wid] = ex;
        __syncthreads();
        if (j == 0) {
            float s = (warpsum[0] + warpsum[1]) + (warpsum[2] + warpsum[3]);
            g_part[b] = mx + __logf(s);
        }
    }

    // ---- gold score for this batch (dtype-adaptive tag/mask reads) ----
    {
        const int tags64 = sh_tags64;   // written in prologue; bars since
        const int mask4 = sh_mask4;
        const long long* tg64 = (const long long*)tags_raw + (size_t)b * SS;
        const int* tg32 = (const int*)tags_raw + (size_t)b * SS;
        const int* mk32 = (const int*)mask_raw + (size_t)b * SS;
        const unsigned char* mk8 = (const unsigned char*)mask_raw + (size_t)b * SS;
        const float* em_row = emissions + (size_t)b * SS * NT;

        float g = 0.f;
        for (int t = j; t < SS; t += NT) {
            int tg = tags64 ? (int)tg64[t] : tg32[t];
            int mraw = mask4 ? mk32[t] : (int)mk8[t];
            float mk = mraw ? 1.f : 0.f;
            g += em_row[(size_t)t * NT + tg] * mk;
            if (t > 0) {
                int tp = tags64 ? (int)tg64[t - 1] : tg32[t - 1];
                g += trans[tp * NT + tg] * mk;
            }
        }
#pragma unroll
        for (int o = 16; o; o >>= 1)
            g += __shfl_xor_sync(0xffffffffu, g, o);
        __syncthreads();   // warpred free for reuse after this
        if (lane == 0) warpred[wid] = g;
        __syncthreads();
        if (j == 0)
            g_gold[b] = (warpred[0] + warpred[1]) + (warpred[2] + warpred[3]);
    }
}

// Deterministic final reduction: out = sum_b (part[b] - gold[b]).
__global__ void finish_kernel(float* __restrict__ out) {
    const int b = threadIdx.x;         // 256 threads
    const int lane = b & 31;
    const int wid = b >> 5;
    __shared__ float wsum[8];
    float v = g_part[b] - g_gold[b];
#pragma unroll
    for (int o = 16; o; o >>= 1)
        v += __shfl_xor_sync(0xffffffffu, v, o);
    if (lane == 0) wsum[wid] = v;
    __syncthreads();
    if (b == 0) {
        float s = 0.f;
#pragma unroll
        for (int w = 0; w < 8; w++) s += wsum[w];
        out[0] = s;
    }
}

extern "C" void kernel_launch(void* const* d_in, const int* in_sizes, int n_in,
                              void* d_out, int out_size) {
    const float* emissions = (const float*)d_in[0];
    const void* tags = d_in[1];
    const void* mask = d_in[2];
    const float* trans = (const float*)d_in[3];
    float* out = (float*)d_out;

    crf_forward_kernel<<<BB, NT>>>(emissions, tags, mask, trans);
    finish_kernel<<<1, BB>>>(out);
}

// round 11
// speedup vs baseline: 1.2385x; 1.0260x over previous
#include <cuda_runtime.h>

#define NT 128
#define BB 256
#define SS 512

__device__ float g_part[BB];
__device__ float g_gold[BB];

// ---- packed fp32x2 helpers (sm_100+; ptxas never auto-fuses these) ----
__device__ __forceinline__ unsigned long long pack2(float lo, float hi) {
    unsigned long long r;
    asm("mov.b64 %0, {%1, %2};" : "=l"(r) : "f"(lo), "f"(hi));
    return r;
}
#define FMA2(acc, a, b) \
    asm("fma.rn.f32x2 %0, %1, %2, %0;" : "+l"(acc) : "l"(a), "l"(b))
__device__ __forceinline__ unsigned long long add2(unsigned long long a,
                                                   unsigned long long b) {
    unsigned long long d;
    asm("add.rn.f32x2 %0, %1, %2;" : "=l"(d) : "l"(a), "l"(b));
    return d;
}
__device__ __forceinline__ float hadd2(unsigned long long a) {
    float lo, hi;
    asm("mov.b64 {%0, %1}, %2;" : "=f"(lo), "=f"(hi) : "l"(a));
    return lo + hi;
}

// One CTA per batch. Thread j owns tag column j; exp(T[:,j]) packed in 64 regs.
// Scaled-domain recurrence: v' = (v @ expT) * exp(ds + e). No per-thread log
// in the loop; only thread 0 takes a log (one step of slack) to produce the
// next shift. exp factor overlaps the FMA tree (independent of it).
__global__ __launch_bounds__(128, 2) void crf_forward_kernel(
    const float* __restrict__ emissions,      // [B, S, NT]
    const void* __restrict__ tags_raw,        // [B, S] int32 or int64
    const void* __restrict__ mask_raw,        // [B, S] 1B or 4B bool
    const float* __restrict__ trans)          // [NT, NT]
{
    const int b = blockIdx.x;
    const int j = threadIdx.x;
    const int lane = j & 31;
    const int wid = j >> 5;

    __shared__ __align__(16) float vsh[2][NT];
    __shared__ float msh[2];
    __shared__ float warpred[4];
    __shared__ float warpsum[4];
    __shared__ int sh_tags64, sh_mask4;

    // ---- dtype detection (JAX x64-off silently makes int64 -> int32) ----
    if (j == 0) {
        const unsigned int* tw = (const unsigned int*)tags_raw;
        int is64 = 1;
        for (int k = 0; k < 32; k++)
            if (tw[2 * k + 1] != 0u) is64 = 0;
        sh_tags64 = is64;
        unsigned int w0 = ((const unsigned int*)mask_raw)[0];
        sh_mask4 = (w0 & 0xFFFFFF00u) ? 0 : 1;
    }

    // ---- build exp(T) column j in packed registers directly from trans ----
    unsigned long long eTp[NT / 2];
#pragma unroll
    for (int i = 0; i < NT / 2; i++)
        eTp[i] = pack2(__expf(trans[(2 * i) * NT + j]),
                       __expf(trans[(2 * i + 1) * NT + j]));

    const float* e_ptr = emissions + (size_t)b * SS * NT;
    float alpha0 = e_ptr[j];           // alpha0 = emissions[b, 0, :]

    if (j == 0) msh[0] = alpha0;       // initial shift broadcast
    __syncthreads();
    const float a0 = msh[0];

    float v_reg = __expf(alpha0 - a0); // v_0
    float s_prev = a0;                 // shift of v_0
    float a0_pend = a0;                // thread0: value to broadcast at iter 1

    // depth-2 emission prefetch: e_cur = row1, e_n1 = row2, e_ptr -> row3
    float e_cur = e_ptr[NT + j];
    float e_n1 = e_ptr[2 * NT + j];
    e_ptr += 3 * NT;

    float w = 0.f, s_used = 0.f, e_used = 0.f;

    // ---- forward recursion, 511 steps; ONE sync per step ----
    int buf = 0;
#pragma unroll 2
    for (int t = 1; t < SS; t++) {
        float e_n2 = 0.f;
        if (t + 2 < SS) { e_n2 = e_ptr[j]; e_ptr += NT; }

        vsh[buf][j] = v_reg;
        if (j == 0) msh[buf] = a0_pend;
        __syncthreads();
        float s_new = msh[buf];

        // exp factor is independent of the FMA tree -> overlaps it
        float expfac = __expf((s_prev - s_new) + e_cur);

        // w[j] = sum_i v[i] * expT[i][j], packed 2-wide, 8 accumulators
        unsigned long long c0 = 0ull, c1 = 0ull, c2 = 0ull, c3 = 0ull;
        unsigned long long c4 = 0ull, c5 = 0ull, c6 = 0ull, c7 = 0ull;
        const ulonglong2* v2 = (const ulonglong2*)vsh[buf];
#pragma unroll
        for (int i = 0; i < 8; i++) {
            ulonglong2 pa = v2[4 * i + 0];
            ulonglong2 pb = v2[4 * i + 1];
            ulonglong2 pc = v2[4 * i + 2];
            ulonglong2 pd = v2[4 * i + 3];
            FMA2(c0, pa.x, eTp[8 * i + 0]);
            FMA2(c1, pa.y, eTp[8 * i + 1]);
            FMA2(c2, pb.x, eTp[8 * i + 2]);
            FMA2(c3, pb.y, eTp[8 * i + 3]);
            FMA2(c4, pc.x, eTp[8 * i + 4]);
            FMA2(c5, pc.y, eTp[8 * i + 5]);
            FMA2(c6, pd.x, eTp[8 * i + 6]);
            FMA2(c7, pd.y, eTp[8 * i + 7]);
        }
        w = hadd2(add2(add2(add2(c0, c1), add2(c2, c3)),
                       add2(add2(c4, c5), add2(c6, c7))));

        v_reg = w * expfac;            // v_t (no log on this path)

        if (j == 0)                    // next shift; one full step of slack
            a0_pend = s_prev + __logf(w) + e_cur;

        s_used = s_prev; e_used = e_cur;   // for final alpha after the loop
        s_prev = s_new;
        e_cur = e_n1;
        e_n1 = e_n2;
        buf ^= 1;
    }

    // ---- final alpha and exact logsumexp over it ----
    float alpha = s_used + __logf(w) + e_used;
    {
        float wm = alpha;
#pragma unroll
        for (int o = 16; o; o >>= 1)
            wm = fmaxf(wm, __shfl_xor_sync(0xffffffffu, wm, o));
        if (lane == 0) warpred[wid] = wm;
        __syncthreads();
        float mx = fmaxf(fmaxf(warpred[0], warpred[1]),
                         fmaxf(warpred[2], warpred[3]));
        float ex = __expf(alpha - mx);
#pragma unroll
        for (int o = 16; o; o >>= 1)
            ex += __shfl_xor_sync(0xffffffffu, ex, o);
        if (lane == 0) warpsum[wid] = ex;
        __syncthreads();
        if (j == 0) {
            float s = (warpsum[0] + warpsum[1]) + (warpsum[2] + warpsum[3]);
            g_part[b] = mx + __logf(s);
        }
    }

    // ---- gold score for this batch (dtype-adaptive tag/mask reads) ----
    {
        const int tags64 = sh_tags64;   // written in prologue; bars since
        const int mask4 = sh_mask4;
        const long long* tg64 = (const long long*)tags_raw + (size_t)b * SS;
        const int* tg32 = (const int*)tags_raw + (size_t)b * SS;
        const int* mk32 = (const int*)mask_raw + (size_t)b * SS;
        const unsigned char* mk8 = (const unsigned char*)mask_raw + (size_t)b * SS;
        const float* em_row = emissions + (size_t)b * SS * NT;

        float g = 0.f;
        for (int t = j; t < SS; t += NT) {
            int tg = tags64 ? (int)tg64[t] : tg32[t];
            int mraw = mask4 ? mk32[t] : (int)mk8[t];
            float mk = mraw ? 1.f : 0.f;
            g += em_row[(size_t)t * NT + tg] * mk;
            if (t > 0) {
                int tp = tags64 ? (int)tg64[t - 1] : tg32[t - 1];
                g += trans[tp * NT + tg] * mk;
            }
        }
#pragma unroll
        for (int o = 16; o; o >>= 1)
            g += __shfl_xor_sync(0xffffffffu, g, o);
        __syncthreads();   // warpred free for reuse after this
        if (lane == 0) warpred[wid] = g;
        __syncthreads();
        if (j == 0)
            g_gold[b] = (warpred[0] + warpred[1]) + (warpred[2] + warpred[3]);
    }
}

// Deterministic final reduction: out = sum_b (part[b] - gold[b]).
__global__ void finish_kernel(float* __restrict__ out) {
    const int b = threadIdx.x;         // 256 threads
    const int lane = b & 31;
    const int wid = b >> 5;
    __shared__ float wsum[8];
    float v = g_part[b] - g_gold[b];
#pragma unroll
    for (int o = 16; o; o >>= 1)
        v += __shfl_xor_sync(0xffffffffu, v, o);
    if (lane == 0) wsum[wid] = v;
    __syncthreads();
    if (b == 0) {
        float s = 0.f;
#pragma unroll
        for (int w = 0; w < 8; w++) s += wsum[w];
        out[0] = s;
    }
}

extern "C" void kernel_launch(void* const* d_in, const int* in_sizes, int n_in,
                              void* d_out, int out_size) {
    const float* emissions = (const float*)d_in[0];
    const void* tags = d_in[1];
    const void* mask = d_in[2];
    const float* trans = (const float*)d_in[3];
    float* out = (float*)d_out;

    crf_forward_kernel<<<BB, NT>>>(emissions, tags, mask, trans);
    finish_kernel<<<1, BB>>>(out);
}